// round 3
// baseline (speedup 1.0000x reference)
#include <cuda_runtime.h>

#define BB   256
#define IN   1024
#define OUTN 1024

#define OT 32   // out-cols per block (lane dimension)
#define BT 8    // batch rows per block (2 warps x RB=4)
#define RB 4    // batch rows per thread (register tile)
#define IC 64   // i-chunk

// Scratch for effective weights (__device__ global: no allocation)
__device__ float g_Weff[OUTN * IN];

__device__ __forceinline__ float tanh_fast(float x) {
    float y;
    asm("tanh.approx.f32 %0, %1;" : "=f"(y) : "f"(x));
    return y;
}

// ---------------------------------------------------------------------------
// Kernel 1: W_eff[o,i] = sum_k softmax(f_logits[o,i,:])_k * atom_k(W[o,i])
// atoms = [identity, tanh, sin]. DRAM-bound (~20MB read / 4MB write):
// use fast MUFU math, errors here are ~1e-6 and scale in linearly.
// ---------------------------------------------------------------------------
__global__ __launch_bounds__(256) void weff_kernel(
    const float* __restrict__ W,
    const float* __restrict__ fl)
{
    int idx = blockIdx.x * blockDim.x + threadIdx.x;
    if (idx >= OUTN * IN) return;
    float w  = W[idx];
    float l0 = fl[3 * idx + 0];
    float l1 = fl[3 * idx + 1];
    float l2 = fl[3 * idx + 2];
    float m  = fmaxf(l0, fmaxf(l1, l2));
    float e0 = __expf(l0 - m);
    float e1 = __expf(l1 - m);
    float e2 = __expf(l2 - m);
    float inv = 1.0f / (e0 + e1 + e2);
    float t = tanh_fast(w);   // |w| <= ~0.26: approx is near-exact here
    float s = __sinf(w);
    g_Weff[idx] = (e0 * w + e1 * t + e2 * s) * inv;
}

// ---------------------------------------------------------------------------
// Kernel 2: out[b,o] = sum_i tanh(h[b,i] * W_eff[o,i]) + bias[o]
// 64 threads (2 warps). lane = out col, warp covers 4 batch rows (RB=4).
// Hybrid tanh: per 4 i's, 3 go through MUFU tanh.approx, 1 through a
// degree-7 odd polynomial on the FMA pipe (guarded by warp-uniform
// max|h| < 2.4 so |z| <= 0.63 on the poly path; else MUFU fallback).
// Raises per-SM tanh throughput 16 -> ~21 lane/cyc.
// 1024 blocks -> ~7/SM -> 98.8% wave utilization.
// ---------------------------------------------------------------------------
__global__ __launch_bounds__(64, 8) void qfbn_main_kernel(
    const float* __restrict__ h,
    const float* __restrict__ bias,
    float* __restrict__ out)
{
    __shared__ float ws[IC][OT + 1];   // W_eff chunk, transposed [i][o]
    __shared__ float hs[IC][BT + 1];   // h chunk, transposed [i][b]

    const int lane  = threadIdx.x & 31;
    const int warp  = threadIdx.x >> 5;          // 0..1
    const int b0    = warp * RB;                 // this thread's batch rows
    const int otile = blockIdx.x * OT;
    const int btile = blockIdx.y * BT;

    // degree-7 odd poly for tanh, collocated to be exact-ish on [0, 0.65]
    const float c3 = -0.33333333f;
    const float c5 =  0.13333333f;
    const float c7 = -0.04603800f;

    float acc0 = 0.f, acc1 = 0.f, acc2 = 0.f, acc3 = 0.f;

    for (int i0 = 0; i0 < IN; i0 += IC) {
        // W_eff tile: OT x IC floats = 512 float4 slots over 64 threads
        #pragma unroll
        for (int s = threadIdx.x; s < OT * (IC / 4); s += 64) {
            int o = s >> 4;          // / (IC/4)
            int g = s & 15;
            float4 v = *reinterpret_cast<const float4*>(
                &g_Weff[(otile + o) * IN + i0 + g * 4]);
            ws[g * 4 + 0][o] = v.x;
            ws[g * 4 + 1][o] = v.y;
            ws[g * 4 + 2][o] = v.z;
            ws[g * 4 + 3][o] = v.w;
        }
        // h tile: BT x IC floats = 128 float4 slots over 64 threads
        #pragma unroll
        for (int s = threadIdx.x; s < BT * (IC / 4); s += 64) {
            int b = s >> 4;
            int g = s & 15;
            float4 v = *reinterpret_cast<const float4*>(
                &h[(btile + b) * IN + i0 + g * 4]);
            hs[g * 4 + 0][b] = v.x;
            hs[g * 4 + 1][b] = v.y;
            hs[g * 4 + 2][b] = v.z;
            hs[g * 4 + 3][b] = v.w;
        }
        __syncthreads();

        #pragma unroll
        for (int i = 0; i < IC; i += 4) {
            // --- 3 MUFU i's ---
            #pragma unroll
            for (int k = 0; k < 3; k++) {
                float wk = ws[i + k][lane];        // 128B conflict-free
                float ha = hs[i + k][b0 + 0];      // broadcasts
                float hb = hs[i + k][b0 + 1];
                float hc = hs[i + k][b0 + 2];
                float hd = hs[i + k][b0 + 3];
                acc0 += tanh_fast(ha * wk);
                acc1 += tanh_fast(hb * wk);
                acc2 += tanh_fast(hc * wk);
                acc3 += tanh_fast(hd * wk);
            }
            // --- 1 poly i (FMA pipe), warp-uniform guard on |h| ---
            {
                float wk = ws[i + 3][lane];
                float ha = hs[i + 3][b0 + 0];
                float hb = hs[i + 3][b0 + 1];
                float hc = hs[i + 3][b0 + 2];
                float hd = hs[i + 3][b0 + 3];
                float hm = fmaxf(fmaxf(fabsf(ha), fabsf(hb)),
                                 fmaxf(fabsf(hc), fabsf(hd)));
                if (__builtin_expect(hm >= 2.4f, 0)) {
                    // rare fallback: exact-ish MUFU
                    acc0 += tanh_fast(ha * wk);
                    acc1 += tanh_fast(hb * wk);
                    acc2 += tanh_fast(hc * wk);
                    acc3 += tanh_fast(hd * wk);
                } else {
                    float za = ha * wk, zb = hb * wk, zc = hc * wk, zd = hd * wk;
                    float a2 = za * za, b2 = zb * zb, c2 = zc * zc, d2 = zd * zd;
                    float pa = fmaf(c7, a2, c5);
                    float pb = fmaf(c7, b2, c5);
                    float pc = fmaf(c7, c2, c5);
                    float pd = fmaf(c7, d2, c5);
                    pa = fmaf(pa, a2, c3);
                    pb = fmaf(pb, b2, c3);
                    pc = fmaf(pc, c2, c3);
                    pd = fmaf(pd, d2, c3);
                    float ta = fmaf(pa, a2, 1.0f);
                    float tb = fmaf(pb, b2, 1.0f);
                    float tc = fmaf(pc, c2, 1.0f);
                    float td = fmaf(pd, d2, 1.0f);
                    acc0 = fmaf(za, ta, acc0);
                    acc1 = fmaf(zb, tb, acc1);
                    acc2 = fmaf(zc, tc, acc2);
                    acc3 = fmaf(zd, td, acc3);
                }
            }
        }
        __syncthreads();
    }

    int o  = otile + lane;
    float bv = bias[o];
    out[(btile + b0 + 0) * OUTN + o] = acc0 + bv;
    out[(btile + b0 + 1) * OUTN + o] = acc1 + bv;
    out[(btile + b0 + 2) * OUTN + o] = acc2 + bv;
    out[(btile + b0 + 3) * OUTN + o] = acc3 + bv;
}

// ---------------------------------------------------------------------------
// Inputs (metadata order): h, W, b, f_logits. Output float (B, OUT).
// Graph-capturable: two kernel launches, no sync, no alloc.
// ---------------------------------------------------------------------------
extern "C" void kernel_launch(void* const* d_in, const int* in_sizes, int n_in,
                              void* d_out, int out_size)
{
    const float* h        = (const float*)d_in[0];
    const float* W        = (const float*)d_in[1];
    const float* bias     = (const float*)d_in[2];
    const float* f_logits = (const float*)d_in[3];
    float* out            = (float*)d_out;

    (void)in_sizes; (void)n_in; (void)out_size;

    weff_kernel<<<(OUTN * IN + 255) / 256, 256>>>(W, f_logits);

    dim3 grid(OUTN / OT, BB / BT);   // 32 x 32 = 1024 blocks
    qfbn_main_kernel<<<grid, 64>>>(h, bias, out);
}